// round 10
// baseline (speedup 1.0000x reference)
#include <cuda_runtime.h>
#include <cuda_bf16.h>
#include <cstdint>

// FASTMultiHeadAttention R10: pipelined-P variant of the R6/R8 core.
//   - P-GEMM for slice m+1 runs in iteration m (R slice m+1 rides in tile m's
//     cp.async buffer) -> gather only reads slices stored before the last
//     __syncthreads -> named barrier DELETED, gather LDS issued at iter top.
//   - ring: 4 live slices, 256 slots, slot = (64m + r - c) & 255, PSTR=266.
// B=1, H=8, N=2048, D=64, fp32 in/out, causal.

namespace {
constexpr int H = 8, N = 2048, D = 64;
constexpr int NT = 512;            // 16 warps: 4 wm x 4 wn

constexpr int BUFSZ = 12288;       // floats per buffer: K 4096 | R 4096 | V 4096
constexpr int RING  = 2 * BUFSZ;   // 24576
constexpr int PSTR  = 266;         // 256-slot ring + pad; (PSTR+1)%32=11 gather-friendly
constexpr int DENB  = RING + 64 * PSTR;      // 41600
constexpr int SMEM_FLOATS = DENB + 256;      // 41856
constexpr int SMEM_BYTES  = SMEM_FLOATS * 4; // 167424
constexpr int KSTR = 68;           // epilogue scratch stride
}

// fragment-packed operands (prepass outputs)
__device__ float4 g_qpack[262144];   // (h, mt128, c4, lane32) x {A1,A2}
__device__ float4 g_kpack[262144];   // (h, jb32, c4, col64, t4)  {b0k1,b1k1,b0k2,b1k2}
__device__ float4 g_rpack[32768];    // (db32, c4, row64, t4)
__device__ float4 g_vpack[262144];   // (h, jb32, cj8, ntp4, lane32) tf32 {b0e,b1e,b0o,b1o}

__device__ __forceinline__ void mma16(float* c, const uint32_t* a, uint32_t b0, uint32_t b1)
{
    asm volatile(
        "mma.sync.aligned.m16n8k16.row.col.f32.bf16.bf16.f32 "
        "{%0,%1,%2,%3}, {%4,%5,%6,%7}, {%8,%9}, {%0,%1,%2,%3};"
        : "+f"(c[0]), "+f"(c[1]), "+f"(c[2]), "+f"(c[3])
        : "r"(a[0]), "r"(a[1]), "r"(a[2]), "r"(a[3]), "r"(b0), "r"(b1));
}

__device__ __forceinline__ void mma8(float* c, const uint32_t* a, uint32_t b0, uint32_t b1)
{
    asm volatile(
        "mma.sync.aligned.m16n8k8.row.col.f32.tf32.tf32.f32 "
        "{%0,%1,%2,%3}, {%4,%5,%6,%7}, {%8,%9}, {%0,%1,%2,%3};"
        : "+f"(c[0]), "+f"(c[1]), "+f"(c[2]), "+f"(c[3])
        : "r"(a[0]), "r"(a[1]), "r"(a[2]), "r"(a[3]), "r"(b0), "r"(b1));
}

__device__ __forceinline__ void split_bf16(float x, uint16_t& hi, uint16_t& lo)
{
    __nv_bfloat16 b1 = __float2bfloat16_rn(x);
    float r = x - __bfloat162float(b1);
    __nv_bfloat16 b2 = __float2bfloat16_rn(r);
    hi = __bfloat16_as_ushort(b1);
    lo = __bfloat16_as_ushort(b2);
}

__device__ __forceinline__ uint32_t pk2(uint16_t lo_even, uint16_t hi_odd)
{
    return ((uint32_t)hi_odd << 16) | lo_even;
}

__device__ __forceinline__ uint32_t tf32r(float x)
{
    uint32_t r; asm("cvt.rna.tf32.f32 %0, %1;" : "=r"(r) : "f"(x)); return r;
}

__device__ __forceinline__ void cp16(uint32_t s, const void* g)
{
    asm volatile("cp.async.cg.shared.global [%0], [%1], 16;" :: "r"(s), "l"(g));
}

// ---------------- fused prepass: 2688 blocks x 256 ----------------
//   [0,512) Q  [512,1536) K  [1536,1664) R  [1664,2688) V

__global__ void __launch_bounds__(256)
pp_fused(const float* __restrict__ q, const float* __restrict__ k,
         const float* __restrict__ v, const float* __restrict__ rpe)
{
    const int bid = blockIdx.x;
    if (bid < 512) {
        int idx = bid * 256 + threadIdx.x;
        int lane = idx & 31, c = (idx >> 5) & 3, mt = (idx >> 7) & 127, h = idx >> 14;
        int g = lane >> 2, t4 = lane & 3;
        const float* qh = q + (size_t)h * N * D;
        int r0 = mt * 16 + g;
        int k0 = c * 16 + 2 * t4;
        float x[2][4];
        #pragma unroll
        for (int rr = 0; rr < 2; rr++) {
            const float* row = qh + (size_t)(r0 + 8 * rr) * D;
            x[rr][0] = row[k0];     x[rr][1] = row[k0 + 1];
            x[rr][2] = row[k0 + 8]; x[rr][3] = row[k0 + 9];
        }
        uint16_t hb[2][4], lb[2][4];
        #pragma unroll
        for (int rr = 0; rr < 2; rr++)
            #pragma unroll
            for (int e = 0; e < 4; e++) split_bf16(x[rr][e], hb[rr][e], lb[rr][e]);
        float4 A1, A2;
        A1.x = __uint_as_float(pk2(hb[0][0], hb[0][1]));
        A1.y = __uint_as_float(pk2(hb[1][0], hb[1][1]));
        A1.z = __uint_as_float(pk2(hb[0][2], hb[0][3]));
        A1.w = __uint_as_float(pk2(hb[1][2], hb[1][3]));
        A2.x = __uint_as_float(pk2(lb[0][0], lb[0][1]));
        A2.y = __uint_as_float(pk2(lb[1][0], lb[1][1]));
        A2.z = __uint_as_float(pk2(lb[0][2], lb[0][3]));
        A2.w = __uint_as_float(pk2(lb[1][2], lb[1][3]));
        g_qpack[idx * 2]     = A1;
        g_qpack[idx * 2 + 1] = A2;
    } else if (bid < 1536) {
        int idx = (bid - 512) * 256 + threadIdx.x;
        int t4 = idx & 3, col = (idx >> 2) & 63, c = (idx >> 8) & 3;
        int jb = (idx >> 10) & 31, h = idx >> 15;
        const float* row = k + ((size_t)h * N + jb * 64 + col) * D;
        int k0 = c * 16 + 2 * t4;
        float y0 = row[k0], y1 = row[k0 + 1], y2 = row[k0 + 8], y3 = row[k0 + 9];
        uint16_t h0, l0, h1, l1, h2, l2, h3, l3;
        split_bf16(y0, h0, l0); split_bf16(y1, h1, l1);
        split_bf16(y2, h2, l2); split_bf16(y3, h3, l3);
        float4 o;
        o.x = __uint_as_float(pk2(h0, h1));
        o.y = __uint_as_float(pk2(h2, h3));
        o.z = __uint_as_float(pk2(l0, l1));
        o.w = __uint_as_float(pk2(l2, l3));
        g_kpack[idx] = o;
    } else if (bid < 1664) {
        int idx = (bid - 1536) * 256 + threadIdx.x;
        int t4 = idx & 3, row = (idx >> 2) & 63, c = (idx >> 8) & 3, db = idx >> 10;
        int t = db * 64 + row;
        const float* src = rpe + (size_t)(t + N - 1) * D;
        int k0 = c * 16 + 2 * t4;
        float y0 = src[k0], y1 = src[k0 + 1], y2 = src[k0 + 8], y3 = src[k0 + 9];
        uint16_t h0, l0, h1, l1, h2, l2, h3, l3;
        split_bf16(y0, h0, l0); split_bf16(y1, h1, l1);
        split_bf16(y2, h2, l2); split_bf16(y3, h3, l3);
        float4 o;
        o.x = __uint_as_float(pk2(h0, h1));
        o.y = __uint_as_float(pk2(h2, h3));
        o.z = __uint_as_float(pk2(l0, l1));
        o.w = __uint_as_float(pk2(l2, l3));
        g_rpack[idx] = o;
    } else {
        int idx = (bid - 1664) * 256 + threadIdx.x;
        int lane = idx & 31, ntp = (idx >> 5) & 3, cj = (idx >> 7) & 7;
        int jb = (idx >> 10) & 31, h = idx >> 15;
        int g = lane >> 2, t4 = lane & 3;
        const float* vh = v + (size_t)h * N * D;
        int j0 = jb * 64 + cj * 8;
        int dc = 16 * ntp + g;
        float4 o;
        o.x = __uint_as_float(tf32r(vh[(size_t)(j0 + t4) * D + dc]));
        o.y = __uint_as_float(tf32r(vh[(size_t)(j0 + t4 + 4) * D + dc]));
        o.z = __uint_as_float(tf32r(vh[(size_t)(j0 + t4) * D + dc + 8]));
        o.w = __uint_as_float(tf32r(vh[(size_t)(j0 + t4 + 4) * D + dc + 8]));
        g_vpack[idx] = o;
    }
}

// ---------------- main kernel ----------------

__global__ void __launch_bounds__(NT, 1)
fastmax_bf16x2_kernel(float* __restrict__ out)
{
    extern __shared__ float sm[];
    uint32_t smb;
    asm("{.reg .u64 t; cvta.to.shared.u64 t, %1; cvt.u32.u64 %0, t;}"
        : "=r"(smb) : "l"(sm));

    const int tid  = threadIdx.x;
    const int lane = tid & 31;
    const int wid  = tid >> 5;
    const int g    = lane >> 2;
    const int t4   = lane & 3;
    const int wm   = wid & 3;
    const int wn   = wid >> 2;

    // 144-CTA balanced schedule: ib 28..31 solo, (27-p, p) pairs
    const int bx = blockIdx.x;
    int h, ib0, ib1, npass;
    if (bx < 32) {
        h = bx >> 2; ib0 = 28 + (bx & 3); ib1 = 0; npass = 1;
    } else {
        int c = bx - 32;
        h = c / 14;
        int p = c % 14;
        ib0 = 27 - p; ib1 = p; npass = 2;
    }

    float* sps = sm + RING;
    const int prow0 = 16 * wm + g;
    float* psrow0 = sps + prow0 * PSTR;
    float* psrow1 = sps + (prow0 + 8) * PSTR;
    float* op = out + (size_t)h * N * D;

    #pragma unroll 1
    for (int pass = 0; pass < npass; pass++) {
        const int ib = pass ? ib1 : ib0;
        const int i0 = ib * 64;

        // Q fragments (persistent in registers)
        uint32_t qa1[4][4], qa2[4][4];
        #pragma unroll
        for (int c = 0; c < 4; c++) {
            const float4* src = &g_qpack[(((size_t)(h * 128 + ib * 4 + wm) * 4 + c) * 32 + lane) * 2];
            float4 A1 = src[0], A2 = src[1];
            qa1[c][0] = __float_as_uint(A1.x); qa1[c][1] = __float_as_uint(A1.y);
            qa1[c][2] = __float_as_uint(A1.z); qa1[c][3] = __float_as_uint(A1.w);
            qa2[c][0] = __float_as_uint(A2.x); qa2[c][1] = __float_as_uint(A2.y);
            qa2[c][2] = __float_as_uint(A2.z); qa2[c][3] = __float_as_uint(A2.w);
        }

        float oacc[8][4];
        #pragma unroll
        for (int nt = 0; nt < 8; nt++)
            #pragma unroll
            for (int c = 0; c < 4; c++) oacc[nt][c] = 0.f;
        float den0 = 0.f, den1 = 0.f;

        // ---- prologue: buf0 <- K(ib), R-slice1, V(ib); buf1.R <- R-slice0 ----
        {
            const float4* gk  = g_kpack + (size_t)(h * 32 + ib) * 1024;
            const float4* gv  = g_vpack + (size_t)(h * 32 + ib) * 1024;
            const float4* gr1 = g_rpack + 1024;   // slice 1 (unused if ib==0)
            const float4* gr0 = g_rpack;          // slice 0
            for (int t = tid; t < 1024; t += NT) {
                cp16(smb + t * 16,         gk  + t);
                cp16(smb + 16384 + t * 16, gr1 + t);
                cp16(smb + 32768 + t * 16, gv  + t);
                cp16(smb + 65536 + t * 16, gr0 + t);   // buf1's R area
            }
            asm volatile("cp.async.commit_group;" ::: "memory");
            asm volatile("cp.async.wait_group 0;" ::: "memory");
            __syncthreads();
        }
        // ---- prologue P-GEMM: slice 0 -> ring base 0 ----
        {
            const uint4* rb4p = (const uint4*)(sm + 16384);
            float pacc[2][4];
            #pragma unroll
            for (int nt = 0; nt < 2; nt++)
                #pragma unroll
                for (int c = 0; c < 4; c++) pacc[nt][c] = 0.f;
            #pragma unroll
            for (int c = 0; c < 4; c++) {
                #pragma unroll
                for (int nt = 0; nt < 2; nt++) {
                    int fi = (c * 64 + 16 * wn + 8 * nt + g) * 4 + t4;
                    uint4 rfr = rb4p[fi];
                    mma16(pacc[nt], qa1[c], rfr.x, rfr.y);
                    mma16(pacc[nt], qa2[c], rfr.x, rfr.y);
                    mma16(pacc[nt], qa1[c], rfr.z, rfr.w);
                }
            }
            #pragma unroll
            for (int nt = 0; nt < 2; nt++) {
                int dl = 16 * wn + 8 * nt + 2 * t4;
                *(float2*)&psrow0[dl] = make_float2(pacc[nt][0], pacc[nt][1]);
                *(float2*)&psrow1[dl] = make_float2(pacc[nt][2], pacc[nt][3]);
            }
        }
        __syncthreads();   // slice-0 visible to all

        for (int m = 0; m <= ib; m++) {
            if (m > 0) {
                asm volatile("cp.async.wait_group 0;" ::: "memory");
                __syncthreads();            // buf[m&1] + ring slice m ready
            }

            const uint4* kb4 = (const uint4*)(sm + (m & 1) * BUFSZ);
            const uint4* rb4 = kb4 + 1024;
            const uint4* vb4 = (const uint4*)(sm + (m & 1) * BUFSZ + 8192);

            // ---- early gather (slices m-1, m; masked cells read garbage) ----
            float pg[2][4];
            {
                const int d0b = 64 * m + prow0 - 16 * wn - 2 * t4;
                #pragma unroll
                for (int nt = 0; nt < 2; nt++) {
                    int dn = d0b - 8 * nt;
                    pg[nt][0] = psrow0[(dn)     & 255];
                    pg[nt][1] = psrow0[(dn - 1) & 255];
                    pg[nt][2] = psrow1[(dn + 8) & 255];
                    pg[nt][3] = psrow1[(dn + 7) & 255];
                }
            }

            if (m < ib) {                   // prefetch next tile
                const int jb = ib - m - 1;
                const int s2 = (m + 2 < 32) ? (m + 2) : 31;     // clamped, unused at edge
                const float4* gk = g_kpack + (size_t)(h * 32 + jb) * 1024;
                const float4* gr = g_rpack + (size_t)s2 * 1024;
                const float4* gv = g_vpack + (size_t)(h * 32 + jb) * 1024;
                uint32_t sb = smb + ((m + 1) & 1) * (BUFSZ * 4);
                for (int t = tid; t < 1024; t += NT) {
                    cp16(sb + t * 16,         gk + t);
                    cp16(sb + 16384 + t * 16, gr + t);
                    cp16(sb + 32768 + t * 16, gv + t);
                }
                asm volatile("cp.async.commit_group;" ::: "memory");
            }

            // ---- P-GEMM slice m+1 (consumed next iter; no barrier needed) ----
            if (m < ib) {
                float pacc[2][4];
                #pragma unroll
                for (int nt = 0; nt < 2; nt++)
                    #pragma unroll
                    for (int c = 0; c < 4; c++) pacc[nt][c] = 0.f;
                #pragma unroll
                for (int c = 0; c < 4; c++) {
                    #pragma unroll
                    for (int nt = 0; nt < 2; nt++) {
                        int fi = (c * 64 + 16 * wn + 8 * nt + g) * 4 + t4;
                        uint4 rfr = rb4[fi];
                        mma16(pacc[nt], qa1[c], rfr.x, rfr.y);
                        mma16(pacc[nt], qa2[c], rfr.x, rfr.y);
                        mma16(pacc[nt], qa1[c], rfr.z, rfr.w);
                    }
                }
                const int bslot = (64 * (m + 1)) & 255;
                #pragma unroll
                for (int nt = 0; nt < 2; nt++) {
                    int dl = 16 * wn + 8 * nt + 2 * t4;
                    *(float2*)&psrow0[bslot + dl] = make_float2(pacc[nt][0], pacc[nt][1]);
                    *(float2*)&psrow1[bslot + dl] = make_float2(pacc[nt][2], pacc[nt][3]);
                }
            }

            // ---- S = Q x K^T (bf16x2: hh + lh + hl) ----
            float sacc[2][4];
            #pragma unroll
            for (int nt = 0; nt < 2; nt++)
                #pragma unroll
                for (int c = 0; c < 4; c++) sacc[nt][c] = 0.f;
            #pragma unroll
            for (int c = 0; c < 4; c++) {
                #pragma unroll
                for (int nt = 0; nt < 2; nt++) {
                    int fi = (c * 64 + 16 * wn + 8 * nt + g) * 4 + t4;
                    uint4 kf = kb4[fi];
                    mma16(sacc[nt], qa1[c], kf.x, kf.y);
                    mma16(sacc[nt], qa2[c], kf.x, kf.y);
                    mma16(sacc[nt], qa1[c], kf.z, kf.w);
                }
            }

            // ---- s += pg; w = 1+s+s^2/2; causal; den from rounded w ----
            uint32_t wt[2][4];
            #pragma unroll
            for (int nt = 0; nt < 2; nt++) {
                int colb = 16 * wn + 8 * nt + 2 * t4;
                #pragma unroll
                for (int c = 0; c < 4; c++) {
                    int row_l = prow0 + ((c >> 1) << 3);
                    int col_l = colb + (c & 1);
                    float s = sacc[nt][c] + pg[nt][c];
                    float w = fmaf(s, fmaf(s, 0.5f, 1.0f), 1.0f);
                    if (m == 0 && col_l > row_l) w = 0.0f;
                    uint32_t wu = tf32r(w);
                    wt[nt][c] = wu;
                    if (c < 2) den0 += __uint_as_float(wu);
                    else       den1 += __uint_as_float(wu);
                }
            }

            // ---- O += W x V (A-frags via shuffles; V single tf32, LDS.128) ----
            #pragma unroll
            for (int kk = 0; kk < 2; kk++) {
                const int src = 4 * g + (t4 >> 1);
                uint32_t v00  = __shfl_sync(0xffffffffu, wt[kk][0], src);
                uint32_t v01  = __shfl_sync(0xffffffffu, wt[kk][1], src);
                uint32_t v20  = __shfl_sync(0xffffffffu, wt[kk][2], src);
                uint32_t v21  = __shfl_sync(0xffffffffu, wt[kk][3], src);
                uint32_t v00b = __shfl_sync(0xffffffffu, wt[kk][0], src + 2);
                uint32_t v01b = __shfl_sync(0xffffffffu, wt[kk][1], src + 2);
                uint32_t v20b = __shfl_sync(0xffffffffu, wt[kk][2], src + 2);
                uint32_t v21b = __shfl_sync(0xffffffffu, wt[kk][3], src + 2);
                uint32_t a[4];
                const bool odd = (t4 & 1);
                a[0] = odd ? v01  : v00;
                a[1] = odd ? v21  : v20;
                a[2] = odd ? v01b : v00b;
                a[3] = odd ? v21b : v20b;
                const int cj = 2 * wn + kk;
                #pragma unroll
                for (int ntp = 0; ntp < 4; ntp++) {
                    uint4 vf = vb4[(cj * 4 + ntp) * 32 + lane];
                    mma8(oacc[2 * ntp],     a, vf.x, vf.y);
                    mma8(oacc[2 * ntp + 1], a, vf.z, vf.w);
                }
            }
        }

        // ---- epilogue: den lane-reduce, combine 4 wn partials, write ----
        den0 += __shfl_xor_sync(0xffffffffu, den0, 1);
        den0 += __shfl_xor_sync(0xffffffffu, den0, 2);
        den1 += __shfl_xor_sync(0xffffffffu, den1, 1);
        den1 += __shfl_xor_sync(0xffffffffu, den1, 2);

        __syncthreads();                 // all smem reads of final tile done
        float* ob1  = sm;                // scratch over buffer region
        float* ob2  = sm + 4352;
        float* ob3  = sm + 8704;
        float* denb = sm + DENB;

        if (wn > 0) {
            float* ob = (wn == 1) ? ob1 : (wn == 2) ? ob2 : ob3;
            #pragma unroll
            for (int nt = 0; nt < 8; nt++) {
                int dcol = 8 * nt + 2 * t4;
                *(float2*)&ob[prow0 * KSTR + dcol]       = make_float2(oacc[nt][0], oacc[nt][1]);
                *(float2*)&ob[(prow0 + 8) * KSTR + dcol] = make_float2(oacc[nt][2], oacc[nt][3]);
            }
            if (t4 == 0) {
                denb[prow0 * 4 + wn]       = den0;
                denb[(prow0 + 8) * 4 + wn] = den1;
            }
        }
        __syncthreads();
        if (wn == 0) {
            float d0 = den0 + denb[prow0 * 4 + 1] + denb[prow0 * 4 + 2] + denb[prow0 * 4 + 3];
            float d1 = den1 + denb[(prow0 + 8) * 4 + 1] + denb[(prow0 + 8) * 4 + 2]
                            + denb[(prow0 + 8) * 4 + 3];
            float inv0 = 1.0f / d0;
            float inv1 = 1.0f / d1;
            #pragma unroll
            for (int nt = 0; nt < 8; nt++) {
                int dcol = 8 * nt + 2 * t4;
                float2 p1 = *(const float2*)&ob1[prow0 * KSTR + dcol];
                float2 p2 = *(const float2*)&ob2[prow0 * KSTR + dcol];
                float2 p3 = *(const float2*)&ob3[prow0 * KSTR + dcol];
                float2 q1 = *(const float2*)&ob1[(prow0 + 8) * KSTR + dcol];
                float2 q2 = *(const float2*)&ob2[(prow0 + 8) * KSTR + dcol];
                float2 q3 = *(const float2*)&ob3[(prow0 + 8) * KSTR + dcol];
                float2 o0 = make_float2((oacc[nt][0] + p1.x + p2.x + p3.x) * inv0,
                                        (oacc[nt][1] + p1.y + p2.y + p3.y) * inv0);
                float2 o1 = make_float2((oacc[nt][2] + q1.x + q2.x + q3.x) * inv1,
                                        (oacc[nt][3] + q1.y + q2.y + q3.y) * inv1);
                *(float2*)&op[(size_t)(i0 + prow0) * D + dcol]     = o0;
                *(float2*)&op[(size_t)(i0 + prow0 + 8) * D + dcol] = o1;
            }
        }
        __syncthreads();                 // scratch free before next pass prologue
    }
}

extern "C" void kernel_launch(void* const* d_in, const int* in_sizes, int n_in,
                              void* d_out, int out_size)
{
    (void)in_sizes; (void)n_in; (void)out_size;
    const float* q   = (const float*)d_in[0];
    const float* k   = (const float*)d_in[1];
    const float* v   = (const float*)d_in[2];
    const float* rpe = (const float*)d_in[3];
    float* out = (float*)d_out;

    pp_fused<<<2688, 256>>>(q, k, v, rpe);

    cudaFuncSetAttribute(fastmax_bf16x2_kernel,
                         cudaFuncAttributeMaxDynamicSharedMemorySize, SMEM_BYTES);
    fastmax_bf16x2_kernel<<<144, NT, SMEM_BYTES>>>(out);
}

// round 11
// speedup vs baseline: 1.5722x; 1.5722x over previous
#include <cuda_runtime.h>
#include <cuda_bf16.h>
#include <cstdint>

// FASTMultiHeadAttention R11: R6 core restored exactly (fused S+P GEMM loop,
// K/R/V cp.async double-buffer, named-bar ring visibility), plus ONLY:
//   - V packed for LDS.128 fragment loads (8 wide loads vs 16 LDS.64)
//   - ring PSTR=138 (near-conflict-free gather banks)
// B=1, H=8, N=2048, D=64, fp32 in/out, causal.

namespace {
constexpr int H = 8, N = 2048, D = 64;
constexpr int NT = 512;            // 16 warps: 4 wm x 4 wn

constexpr int BUFSZ = 12288;       // floats per buffer: K 4096 | R 4096 | V 4096
constexpr int RING  = 2 * BUFSZ;   // 24576
constexpr int PSTR  = 138;
constexpr int DENB  = RING + 64 * PSTR;      // 33408
constexpr int SMEM_FLOATS = DENB + 256;      // 33664
constexpr int SMEM_BYTES  = SMEM_FLOATS * 4; // 134656
constexpr int KSTR = 68;           // epilogue scratch stride
}

// fragment-packed operands (prepass outputs)
__device__ float4 g_qpack[262144];   // (h, mt128, c4, lane32) x {A1,A2}
__device__ float4 g_kpack[262144];   // (h, jb32, c4, col64, t4)  {b0k1,b1k1,b0k2,b1k2}
__device__ float4 g_rpack[32768];    // (db32, c4, row64, t4)
__device__ float4 g_vpack[262144];   // (h, jb32, cj8, ntp4, lane32) tf32 {b0e,b1e,b0o,b1o}

__device__ __forceinline__ void mma16(float* c, const uint32_t* a, uint32_t b0, uint32_t b1)
{
    asm volatile(
        "mma.sync.aligned.m16n8k16.row.col.f32.bf16.bf16.f32 "
        "{%0,%1,%2,%3}, {%4,%5,%6,%7}, {%8,%9}, {%0,%1,%2,%3};"
        : "+f"(c[0]), "+f"(c[1]), "+f"(c[2]), "+f"(c[3])
        : "r"(a[0]), "r"(a[1]), "r"(a[2]), "r"(a[3]), "r"(b0), "r"(b1));
}

__device__ __forceinline__ void mma8(float* c, const uint32_t* a, uint32_t b0, uint32_t b1)
{
    asm volatile(
        "mma.sync.aligned.m16n8k8.row.col.f32.tf32.tf32.f32 "
        "{%0,%1,%2,%3}, {%4,%5,%6,%7}, {%8,%9}, {%0,%1,%2,%3};"
        : "+f"(c[0]), "+f"(c[1]), "+f"(c[2]), "+f"(c[3])
        : "r"(a[0]), "r"(a[1]), "r"(a[2]), "r"(a[3]), "r"(b0), "r"(b1));
}

__device__ __forceinline__ void split_bf16(float x, uint16_t& hi, uint16_t& lo)
{
    __nv_bfloat16 b1 = __float2bfloat16_rn(x);
    float r = x - __bfloat162float(b1);
    __nv_bfloat16 b2 = __float2bfloat16_rn(r);
    hi = __bfloat16_as_ushort(b1);
    lo = __bfloat16_as_ushort(b2);
}

__device__ __forceinline__ uint32_t pk2(uint16_t lo_even, uint16_t hi_odd)
{
    return ((uint32_t)hi_odd << 16) | lo_even;
}

__device__ __forceinline__ uint32_t tf32r(float x)
{
    uint32_t r; asm("cvt.rna.tf32.f32 %0, %1;" : "=r"(r) : "f"(x)); return r;
}

__device__ __forceinline__ void cp16(uint32_t s, const void* g)
{
    asm volatile("cp.async.cg.shared.global [%0], [%1], 16;" :: "r"(s), "l"(g));
}

// ---------------- fused prepass: 2688 blocks x 256 ----------------
//   [0,512) Q  [512,1536) K  [1536,1664) R  [1664,2688) V

__global__ void __launch_bounds__(256)
pp_fused(const float* __restrict__ q, const float* __restrict__ k,
         const float* __restrict__ v, const float* __restrict__ rpe)
{
    const int bid = blockIdx.x;
    if (bid < 512) {
        int idx = bid * 256 + threadIdx.x;
        int lane = idx & 31, c = (idx >> 5) & 3, mt = (idx >> 7) & 127, h = idx >> 14;
        int g = lane >> 2, t4 = lane & 3;
        const float* qh = q + (size_t)h * N * D;
        int r0 = mt * 16 + g;
        int k0 = c * 16 + 2 * t4;
        float x[2][4];
        #pragma unroll
        for (int rr = 0; rr < 2; rr++) {
            const float* row = qh + (size_t)(r0 + 8 * rr) * D;
            x[rr][0] = row[k0];     x[rr][1] = row[k0 + 1];
            x[rr][2] = row[k0 + 8]; x[rr][3] = row[k0 + 9];
        }
        uint16_t hb[2][4], lb[2][4];
        #pragma unroll
        for (int rr = 0; rr < 2; rr++)
            #pragma unroll
            for (int e = 0; e < 4; e++) split_bf16(x[rr][e], hb[rr][e], lb[rr][e]);
        float4 A1, A2;
        A1.x = __uint_as_float(pk2(hb[0][0], hb[0][1]));
        A1.y = __uint_as_float(pk2(hb[1][0], hb[1][1]));
        A1.z = __uint_as_float(pk2(hb[0][2], hb[0][3]));
        A1.w = __uint_as_float(pk2(hb[1][2], hb[1][3]));
        A2.x = __uint_as_float(pk2(lb[0][0], lb[0][1]));
        A2.y = __uint_as_float(pk2(lb[1][0], lb[1][1]));
        A2.z = __uint_as_float(pk2(lb[0][2], lb[0][3]));
        A2.w = __uint_as_float(pk2(lb[1][2], lb[1][3]));
        g_qpack[idx * 2]     = A1;
        g_qpack[idx * 2 + 1] = A2;
    } else if (bid < 1536) {
        int idx = (bid - 512) * 256 + threadIdx.x;
        int t4 = idx & 3, col = (idx >> 2) & 63, c = (idx >> 8) & 3;
        int jb = (idx >> 10) & 31, h = idx >> 15;
        const float* row = k + ((size_t)h * N + jb * 64 + col) * D;
        int k0 = c * 16 + 2 * t4;
        float y0 = row[k0], y1 = row[k0 + 1], y2 = row[k0 + 8], y3 = row[k0 + 9];
        uint16_t h0, l0, h1, l1, h2, l2, h3, l3;
        split_bf16(y0, h0, l0); split_bf16(y1, h1, l1);
        split_bf16(y2, h2, l2); split_bf16(y3, h3, l3);
        float4 o;
        o.x = __uint_as_float(pk2(h0, h1));
        o.y = __uint_as_float(pk2(h2, h3));
        o.z = __uint_as_float(pk2(l0, l1));
        o.w = __uint_as_float(pk2(l2, l3));
        g_kpack[idx] = o;
    } else if (bid < 1664) {
        int idx = (bid - 1536) * 256 + threadIdx.x;
        int t4 = idx & 3, row = (idx >> 2) & 63, c = (idx >> 8) & 3, db = idx >> 10;
        int t = db * 64 + row;
        const float* src = rpe + (size_t)(t + N - 1) * D;
        int k0 = c * 16 + 2 * t4;
        float y0 = src[k0], y1 = src[k0 + 1], y2 = src[k0 + 8], y3 = src[k0 + 9];
        uint16_t h0, l0, h1, l1, h2, l2, h3, l3;
        split_bf16(y0, h0, l0); split_bf16(y1, h1, l1);
        split_bf16(y2, h2, l2); split_bf16(y3, h3, l3);
        float4 o;
        o.x = __uint_as_float(pk2(h0, h1));
        o.y = __uint_as_float(pk2(h2, h3));
        o.z = __uint_as_float(pk2(l0, l1));
        o.w = __uint_as_float(pk2(l2, l3));
        g_rpack[idx] = o;
    } else {
        int idx = (bid - 1664) * 256 + threadIdx.x;
        int lane = idx & 31, ntp = (idx >> 5) & 3, cj = (idx >> 7) & 7;
        int jb = (idx >> 10) & 31, h = idx >> 15;
        int g = lane >> 2, t4 = lane & 3;
        const float* vh = v + (size_t)h * N * D;
        int j0 = jb * 64 + cj * 8;
        int dc = 16 * ntp + g;
        float4 o;
        o.x = __uint_as_float(tf32r(vh[(size_t)(j0 + t4) * D + dc]));
        o.y = __uint_as_float(tf32r(vh[(size_t)(j0 + t4 + 4) * D + dc]));
        o.z = __uint_as_float(tf32r(vh[(size_t)(j0 + t4) * D + dc + 8]));
        o.w = __uint_as_float(tf32r(vh[(size_t)(j0 + t4 + 4) * D + dc + 8]));
        g_vpack[idx] = o;
    }
}

// ---------------- main kernel ----------------

__global__ void __launch_bounds__(NT, 1)
fastmax_bf16x2_kernel(float* __restrict__ out)
{
    extern __shared__ float sm[];
    uint32_t smb;
    asm("{.reg .u64 t; cvta.to.shared.u64 t, %1; cvt.u32.u64 %0, t;}"
        : "=r"(smb) : "l"(sm));

    const int tid  = threadIdx.x;
    const int lane = tid & 31;
    const int wid  = tid >> 5;
    const int g    = lane >> 2;
    const int t4   = lane & 3;
    const int wm   = wid & 3;
    const int wn   = wid >> 2;

    // 144-CTA balanced schedule: ib 28..31 solo, (27-p, p) pairs
    const int bx = blockIdx.x;
    int h, ib0, ib1, npass;
    if (bx < 32) {
        h = bx >> 2; ib0 = 28 + (bx & 3); ib1 = 0; npass = 1;
    } else {
        int c = bx - 32;
        h = c / 14;
        int p = c % 14;
        ib0 = 27 - p; ib1 = p; npass = 2;
    }

    float* sps = sm + RING;
    const int prow0 = 16 * wm + g;
    float* psrow0 = sps + prow0 * PSTR;
    float* psrow1 = sps + (prow0 + 8) * PSTR;
    float* op = out + (size_t)h * N * D;

    #pragma unroll 1
    for (int pass = 0; pass < npass; pass++) {
        const int ib = pass ? ib1 : ib0;
        const int i0 = ib * 64;

        // Q fragments (persistent in registers)
        uint32_t qa1[4][4], qa2[4][4];
        #pragma unroll
        for (int c = 0; c < 4; c++) {
            const float4* src = &g_qpack[(((size_t)(h * 128 + ib * 4 + wm) * 4 + c) * 32 + lane) * 2];
            float4 A1 = src[0], A2 = src[1];
            qa1[c][0] = __float_as_uint(A1.x); qa1[c][1] = __float_as_uint(A1.y);
            qa1[c][2] = __float_as_uint(A1.z); qa1[c][3] = __float_as_uint(A1.w);
            qa2[c][0] = __float_as_uint(A2.x); qa2[c][1] = __float_as_uint(A2.y);
            qa2[c][2] = __float_as_uint(A2.z); qa2[c][3] = __float_as_uint(A2.w);
        }

        float oacc[8][4];
        #pragma unroll
        for (int nt = 0; nt < 8; nt++)
            #pragma unroll
            for (int c = 0; c < 4; c++) oacc[nt][c] = 0.f;
        float den0 = 0.f, den1 = 0.f;

        // prefetch tile 0 (K + R + V) into buf 0
        {
            const float4* gk = g_kpack + (size_t)(h * 32 + ib) * 1024;
            const float4* gr = g_rpack;
            const float4* gv = g_vpack + (size_t)(h * 32 + ib) * 1024;
            for (int t = tid; t < 1024; t += NT) {
                cp16(smb + t * 16,         gk + t);
                cp16(smb + 16384 + t * 16, gr + t);
                cp16(smb + 32768 + t * 16, gv + t);
            }
            asm volatile("cp.async.commit_group;" ::: "memory");
        }

        for (int m = 0; m <= ib; m++) {
            asm volatile("cp.async.wait_group 0;" ::: "memory");
            __syncthreads();                        // buf[m&1] ready everywhere

            if (m < ib) {                           // prefetch next tile
                const int jb = ib - m - 1;
                const float4* gk = g_kpack + (size_t)(h * 32 + jb) * 1024;
                const float4* gr = g_rpack + (size_t)(m + 1) * 1024;
                const float4* gv = g_vpack + (size_t)(h * 32 + jb) * 1024;
                uint32_t sb = smb + ((m + 1) & 1) * (BUFSZ * 4);
                for (int t = tid; t < 1024; t += NT) {
                    cp16(sb + t * 16,         gk + t);
                    cp16(sb + 16384 + t * 16, gr + t);
                    cp16(sb + 32768 + t * 16, gv + t);
                }
                asm volatile("cp.async.commit_group;" ::: "memory");
            }

            const uint4* kb4 = (const uint4*)(sm + (m & 1) * BUFSZ);
            const uint4* rb4 = kb4 + 1024;
            const uint4* vb4 = (const uint4*)(sm + (m & 1) * BUFSZ + 8192);

            // ---- fused S = QK^T and P = QR^T (bf16x2: hh + lh + hl) ----
            float sacc[2][4], pacc[2][4];
            #pragma unroll
            for (int nt = 0; nt < 2; nt++)
                #pragma unroll
                for (int c = 0; c < 4; c++) { sacc[nt][c] = 0.f; pacc[nt][c] = 0.f; }

            #pragma unroll
            for (int c = 0; c < 4; c++) {
                #pragma unroll
                for (int nt = 0; nt < 2; nt++) {
                    int fi = (c * 64 + 16 * wn + 8 * nt + g) * 4 + t4;
                    uint4 kf = kb4[fi];
                    mma16(sacc[nt], qa1[c], kf.x, kf.y);
                    mma16(sacc[nt], qa2[c], kf.x, kf.y);
                    mma16(sacc[nt], qa1[c], kf.z, kf.w);
                    uint4 rfr = rb4[fi];
                    mma16(pacc[nt], qa1[c], rfr.x, rfr.y);
                    mma16(pacc[nt], qa2[c], rfr.x, rfr.y);
                    mma16(pacc[nt], qa1[c], rfr.z, rfr.w);
                }
            }

            // ---- P-new into wm-partitioned 128-slot ring ----
            {
                const int bslot = (64 * m) & 127;
                #pragma unroll
                for (int nt = 0; nt < 2; nt++) {
                    int dl = 16 * wn + 8 * nt + 2 * t4;
                    *(float2*)&psrow0[bslot + dl] = make_float2(pacc[nt][0], pacc[nt][1]);
                    *(float2*)&psrow1[bslot + dl] = make_float2(pacc[nt][2], pacc[nt][3]);
                }
            }
            // ring rows [16wm,16wm+16) produced/consumed only by this wm group
            asm volatile("bar.sync %0, %1;" :: "r"(1 + wm), "r"(128) : "memory");

            // ---- s += P gather; w = 1+s+s^2/2; causal; den from rounded w ----
            uint32_t wt[2][4];
            #pragma unroll
            for (int nt = 0; nt < 2; nt++) {
                int colb = 16 * wn + 8 * nt + 2 * t4;
                #pragma unroll
                for (int c = 0; c < 4; c++) {
                    int row_l = prow0 + ((c >> 1) << 3);
                    int col_l = colb + (c & 1);
                    unsigned slot = (unsigned)(64 * m + row_l - col_l) & 127u;
                    float s = sacc[nt][c] + sps[row_l * PSTR + slot];
                    float w = fmaf(s, fmaf(s, 0.5f, 1.0f), 1.0f);
                    if (m == 0 && col_l > row_l) w = 0.0f;
                    uint32_t wu = tf32r(w);
                    wt[nt][c] = wu;
                    if (c < 2) den0 += __uint_as_float(wu);
                    else       den1 += __uint_as_float(wu);
                }
            }

            // ---- O += W x V (A-frags via shuffles; V single tf32, LDS.128) ----
            #pragma unroll
            for (int kk = 0; kk < 2; kk++) {
                const int src = 4 * g + (t4 >> 1);
                uint32_t v00  = __shfl_sync(0xffffffffu, wt[kk][0], src);
                uint32_t v01  = __shfl_sync(0xffffffffu, wt[kk][1], src);
                uint32_t v20  = __shfl_sync(0xffffffffu, wt[kk][2], src);
                uint32_t v21  = __shfl_sync(0xffffffffu, wt[kk][3], src);
                uint32_t v00b = __shfl_sync(0xffffffffu, wt[kk][0], src + 2);
                uint32_t v01b = __shfl_sync(0xffffffffu, wt[kk][1], src + 2);
                uint32_t v20b = __shfl_sync(0xffffffffu, wt[kk][2], src + 2);
                uint32_t v21b = __shfl_sync(0xffffffffu, wt[kk][3], src + 2);
                uint32_t a[4];
                const bool odd = (t4 & 1);
                a[0] = odd ? v01  : v00;
                a[1] = odd ? v21  : v20;
                a[2] = odd ? v01b : v00b;
                a[3] = odd ? v21b : v20b;
                const int cj = 2 * wn + kk;
                #pragma unroll
                for (int ntp = 0; ntp < 4; ntp++) {
                    uint4 vf = vb4[(cj * 4 + ntp) * 32 + lane];
                    mma8(oacc[2 * ntp],     a, vf.x, vf.y);
                    mma8(oacc[2 * ntp + 1], a, vf.z, vf.w);
                }
            }
        }

        // ---- epilogue: den lane-reduce, combine 4 wn partials, write ----
        den0 += __shfl_xor_sync(0xffffffffu, den0, 1);
        den0 += __shfl_xor_sync(0xffffffffu, den0, 2);
        den1 += __shfl_xor_sync(0xffffffffu, den1, 1);
        den1 += __shfl_xor_sync(0xffffffffu, den1, 2);

        __syncthreads();                 // all smem reads of final tile done
        float* ob1  = sm;                // scratch over buffer region
        float* ob2  = sm + 4352;
        float* ob3  = sm + 8704;
        float* denb = sm + DENB;

        if (wn > 0) {
            float* ob = (wn == 1) ? ob1 : (wn == 2) ? ob2 : ob3;
            #pragma unroll
            for (int nt = 0; nt < 8; nt++) {
                int dcol = 8 * nt + 2 * t4;
                *(float2*)&ob[prow0 * KSTR + dcol]       = make_float2(oacc[nt][0], oacc[nt][1]);
                *(float2*)&ob[(prow0 + 8) * KSTR + dcol] = make_float2(oacc[nt][2], oacc[nt][3]);
            }
            if (t4 == 0) {
                denb[prow0 * 4 + wn]       = den0;
                denb[(prow0 + 8) * 4 + wn] = den1;
            }
        }
        __syncthreads();
        if (wn == 0) {
            float d0 = den0 + denb[prow0 * 4 + 1] + denb[prow0 * 4 + 2] + denb[prow0 * 4 + 3];
            float d1 = den1 + denb[(prow0 + 8) * 4 + 1] + denb[(prow0 + 8) * 4 + 2]
                            + denb[(prow0 + 8) * 4 + 3];
            float inv0 = 1.0f / d0;
            float inv1 = 1.0f / d1;
            #pragma unroll
            for (int nt = 0; nt < 8; nt++) {
                int dcol = 8 * nt + 2 * t4;
                float2 p1 = *(const float2*)&ob1[prow0 * KSTR + dcol];
                float2 p2 = *(const float2*)&ob2[prow0 * KSTR + dcol];
                float2 p3 = *(const float2*)&ob3[prow0 * KSTR + dcol];
                float2 q1 = *(const float2*)&ob1[(prow0 + 8) * KSTR + dcol];
                float2 q2 = *(const float2*)&ob2[(prow0 + 8) * KSTR + dcol];
                float2 q3 = *(const float2*)&ob3[(prow0 + 8) * KSTR + dcol];
                float2 o0 = make_float2((oacc[nt][0] + p1.x + p2.x + p3.x) * inv0,
                                        (oacc[nt][1] + p1.y + p2.y + p3.y) * inv0);
                float2 o1 = make_float2((oacc[nt][2] + q1.x + q2.x + q3.x) * inv1,
                                        (oacc[nt][3] + q1.y + q2.y + q3.y) * inv1);
                *(float2*)&op[(size_t)(i0 + prow0) * D + dcol]     = o0;
                *(float2*)&op[(size_t)(i0 + prow0 + 8) * D + dcol] = o1;
            }
        }
        __syncthreads();                 // scratch free before next pass prefetch
    }
}

extern "C" void kernel_launch(void* const* d_in, const int* in_sizes, int n_in,
                              void* d_out, int out_size)
{
    (void)in_sizes; (void)n_in; (void)out_size;
    const float* q   = (const float*)d_in[0];
    const float* k   = (const float*)d_in[1];
    const float* v   = (const float*)d_in[2];
    const float* rpe = (const float*)d_in[3];
    float* out = (float*)d_out;

    pp_fused<<<2688, 256>>>(q, k, v, rpe);

    cudaFuncSetAttribute(fastmax_bf16x2_kernel,
                         cudaFuncAttributeMaxDynamicSharedMemorySize, SMEM_BYTES);
    fastmax_bf16x2_kernel<<<144, NT, SMEM_BYTES>>>(out);
}